// round 6
// baseline (speedup 1.0000x reference)
#include <cuda_runtime.h>
#include <cstdint>

// ---------------- problem constants ----------------
#define G_    64
#define T_    8192
#define DIN_  2560
#define DOUT_ 1664
#define CAP_  256

// ---------------- tiling ----------------
#define BM 64
#define BN 256
#define BK 16
#define NK (DIN_ / BK)                 // 160
#define NT_N ((DOUT_ + BN - 1) / BN)   // 7 (last tile masked)

#define LDA_B 48                       // A row stride bytes (32 data + 16 pad): 3m%8 distinct
#define LDB_B 528                      // B row stride bytes (512 data + 16 pad): 33k%8 distinct
#define A_SM  (BM * LDA_B)             // 3072
#define B_SM  (BK * LDB_B)             // 8448
#define STG_B (A_SM + B_SM)            // 11520

__device__ int g_starts[G_];

__global__ void starts_kernel(const int* __restrict__ counts) {
    if (threadIdx.x == 0 && blockIdx.x == 0) {
        int s = 0;
        for (int g = 0; g < G_; ++g) { g_starts[g] = s; s += counts[g]; }
    }
}

static __device__ __forceinline__ uint32_t smem_u32(const void* p) {
    uint32_t a;
    asm("{ .reg .u64 t; cvta.to.shared.u64 t, %1; cvt.u32.u64 %0, t; }" : "=r"(a) : "l"(p));
    return a;
}

// pack two f32 -> f16x2 (lo = first arg)
static __device__ __forceinline__ uint32_t pack_h2(float lo, float hi) {
    uint32_t d;
    asm("cvt.rn.f16x2.f32 %0, %1, %2;" : "=r"(d) : "f"(hi), "f"(lo));
    return d;
}

static __device__ __forceinline__ void sts64(uint32_t addr, uint32_t w0, uint32_t w1) {
    asm volatile("st.shared.v2.b32 [%0], {%1, %2};" :: "r"(addr), "r"(w0), "r"(w1));
}

#define LDSM4(r, a) \
    asm volatile("ldmatrix.sync.aligned.m8n8.x4.shared.b16 {%0,%1,%2,%3}, [%4];" \
        : "=r"((r)[0]), "=r"((r)[1]), "=r"((r)[2]), "=r"((r)[3]) : "r"(a))

#define LDSM4T(r, a) \
    asm volatile("ldmatrix.sync.aligned.m8n8.x4.trans.shared.b16 {%0,%1,%2,%3}, [%4];" \
        : "=r"((r)[0]), "=r"((r)[1]), "=r"((r)[2]), "=r"((r)[3]) : "r"(a))

static __device__ __forceinline__ void mma_f16(float* c, const uint32_t* a,
                                               uint32_t b0, uint32_t b1) {
    asm volatile(
        "mma.sync.aligned.m16n8k16.row.col.f32.f16.f16.f32 "
        "{%0,%1,%2,%3}, {%4,%5,%6,%7}, {%8,%9}, {%0,%1,%2,%3};\n"
        : "+f"(c[0]), "+f"(c[1]), "+f"(c[2]), "+f"(c[3])
        : "r"(a[0]), "r"(a[1]), "r"(a[2]), "r"(a[3]), "r"(b0), "r"(b1));
}

__global__ __launch_bounds__(256, 1)
void grouped_gemm_kernel(const float* __restrict__ X, const float* __restrict__ W,
                         const int* __restrict__ counts, float* __restrict__ Y) {
    __shared__ char smem[2 * STG_B];     // [buf][A fp16 | B fp16]

    const int g  = blockIdx.z;
    const int mt = blockIdx.y;
    const int nt = blockIdx.x;
    const int cnt = counts[g];
    if (mt * BM >= cnt) return;
    const int gstart = g_starts[g];

    const int t    = threadIdx.x;
    const int lane = t & 31;
    const int wid  = t >> 5;
    const int warpM = wid & 1;           // 2 warps along M (32 rows)
    const int warpN = wid >> 1;          // 4 warps along N (64 cols)
    const int m0 = warpM * 32;
    const int n0 = warpN * 64;
    const int tg  = lane >> 2;
    const int tig = lane & 3;

    // ---- global load mapping (f32) ----
    // A: 1 float4/thread: row = t>>2 (0..63), kv = t&3 (4 k each)
    const int a_row = t >> 2;
    const int a_kv  = t & 3;
    long long arow = (long long)gstart + mt * BM + a_row;
    if (arow > T_ - 1) arow = T_ - 1;    // clamp; masked in epilogue
    const float* Ag = X + arow * DIN_ + a_kv * 4;
    const uint32_t aDst = (uint32_t)(a_row * LDA_B + a_kv * 8);

    // B: 4 float4/thread: k = (t>>6) + 4*i, n = (t&63)*4
    const int b_k0 = t >> 6;             // 0..3
    const int b_nv = t & 63;
    int bcol = nt * BN + b_nv * 4;
    if (bcol > DOUT_ - 4) bcol = DOUT_ - 4;   // clamp tail tile (smem dst unclamped)
    const float* Bg = W + (long long)g * DIN_ * DOUT_ + bcol;
    const uint32_t bDst = (uint32_t)(b_k0 * LDB_B + b_nv * 8);

    const uint32_t sBase = smem_u32(smem);

    float4 aR, bR[4];
    auto load_g = [&](int kt) {
        const int k0 = kt * BK;
        aR = *(const float4*)(Ag + k0);
        #pragma unroll
        for (int i = 0; i < 4; ++i)
            bR[i] = *(const float4*)(Bg + (long long)(k0 + b_k0 + 4 * i) * DOUT_);
    };
    auto store_s = [&](int buf) {
        const uint32_t stg = sBase + (uint32_t)buf * STG_B;
        sts64(stg + aDst, pack_h2(aR.x, aR.y), pack_h2(aR.z, aR.w));
        #pragma unroll
        for (int i = 0; i < 4; ++i)
            sts64(stg + A_SM + bDst + (uint32_t)(4 * i * LDB_B),
                  pack_h2(bR[i].x, bR[i].y), pack_h2(bR[i].z, bR[i].w));
    };

    // ---- ldmatrix addresses ----
    const int l15 = lane & 15;
    const int lhi = lane >> 4;
    uint32_t aoff[2];
    #pragma unroll
    for (int mf = 0; mf < 2; ++mf)
        aoff[mf] = (uint32_t)((m0 + mf * 16 + l15) * LDA_B + lhi * 16);
    uint32_t boff[4];
    #pragma unroll
    for (int p = 0; p < 4; ++p)
        boff[p] = (uint32_t)(A_SM + l15 * LDB_B + (n0 + p * 16 + lhi * 8) * 2);

    float acc[2][8][4];
    #pragma unroll
    for (int mf = 0; mf < 2; ++mf)
        #pragma unroll
        for (int nf = 0; nf < 8; ++nf)
            #pragma unroll
            for (int i = 0; i < 4; ++i) acc[mf][nf][i] = 0.0f;

    load_g(0);
    store_s(0);
    load_g(1);
    __syncthreads();

    for (int kt = 0; kt < NK; ++kt) {
        const uint32_t stg = sBase + (uint32_t)(kt & 1) * STG_B;

        uint32_t af[2][4], bf[4][4];
        LDSM4(af[0], stg + aoff[0]);
        LDSM4(af[1], stg + aoff[1]);
        #pragma unroll
        for (int p = 0; p < 4; ++p)
            LDSM4T(bf[p], stg + boff[p]);

        #pragma unroll
        for (int p = 0; p < 4; ++p)
            #pragma unroll
            for (int mf = 0; mf < 2; ++mf) {
                mma_f16(acc[mf][2 * p],     af[mf], bf[p][0], bf[p][1]);
                mma_f16(acc[mf][2 * p + 1], af[mf], bf[p][2], bf[p][3]);
            }

        if (kt + 1 < NK) {
            store_s((kt + 1) & 1);       // regs hold stage kt+1
            if (kt + 2 < NK) load_g(kt + 2);
        }
        __syncthreads();
    }

    // ---- epilogue: predicated float2 stores ----
    #pragma unroll
    for (int mf = 0; mf < 2; ++mf) {
        const int r0 = mt * BM + m0 + mf * 16 + tg;
        const int r1 = r0 + 8;
        #pragma unroll
        for (int nf = 0; nf < 8; ++nf) {
            const int col = nt * BN + n0 + nf * 8 + tig * 2;
            if (col < DOUT_) {
                if (r0 < cnt) {
                    float2 v = make_float2(acc[mf][nf][0], acc[mf][nf][1]);
                    *(float2*)&Y[(long long)(gstart + r0) * DOUT_ + col] = v;
                }
                if (r1 < cnt) {
                    float2 v = make_float2(acc[mf][nf][2], acc[mf][nf][3]);
                    *(float2*)&Y[(long long)(gstart + r1) * DOUT_ + col] = v;
                }
            }
        }
    }
}

extern "C" void kernel_launch(void* const* d_in, const int* in_sizes, int n_in,
                              void* d_out, int out_size) {
    const float* x    = (const float*)d_in[0];
    const float* w    = (const float*)d_in[1];
    const int*   cnts = (const int*)d_in[2];
    float* y = (float*)d_out;

    starts_kernel<<<1, 32>>>(cnts);

    dim3 grid(NT_N, CAP_ / BM, G_);      // (7, 4, 64)
    grouped_gemm_kernel<<<grid, 256>>>(x, w, cnts, y);
}

// round 7
// speedup vs baseline: 1.7686x; 1.7686x over previous
#include <cuda_runtime.h>
#include <cstdint>

// ---------------- problem constants ----------------
#define G_    64
#define T_    8192
#define DIN_  2560
#define DOUT_ 1664
#define CAP_  256

// ---------------- tiling ----------------
#define BM 64
#define BN 256
#define BK 16
#define NK (DIN_ / BK)                 // 160
#define NT_N ((DOUT_ + BN - 1) / BN)   // 7 (last tile masked)

// raw f32 staging
#define RAW_A   (BM * BK * 4)          // 4096
#define RAW_B   (BK * BN * 4)          // 16384
#define RAW_STG (RAW_A + RAW_B)        // 20480
#define NSTAGE  3

// fp16 compute buffers
#define LDA_B 48                       // A fp16 row stride (32 data + 16 pad)
#define LDB_B 528                      // B fp16 row stride (512 data + 16 pad)
#define FP_A  (BM * LDA_B)             // 3072
#define FP_B  (BK * LDB_B)             // 8448
#define FP_STG (FP_A + FP_B)           // 11520

#define SMEM_TOTAL (NSTAGE * RAW_STG + 2 * FP_STG)   // 84480

__device__ int g_starts[G_];

__global__ void starts_kernel(const int* __restrict__ counts) {
    if (threadIdx.x == 0 && blockIdx.x == 0) {
        int s = 0;
        for (int g = 0; g < G_; ++g) { g_starts[g] = s; s += counts[g]; }
    }
}

static __device__ __forceinline__ uint32_t smem_u32(const void* p) {
    uint32_t a;
    asm("{ .reg .u64 t; cvta.to.shared.u64 t, %1; cvt.u32.u64 %0, t; }" : "=r"(a) : "l"(p));
    return a;
}

static __device__ __forceinline__ uint32_t pack_h2(float lo, float hi) {
    uint32_t d;
    asm("cvt.rn.f16x2.f32 %0, %1, %2;" : "=r"(d) : "f"(hi), "f"(lo));
    return d;
}

static __device__ __forceinline__ void cp16(uint32_t dst, const void* src) {
    asm volatile("cp.async.cg.shared.global [%0], [%1], 16;" :: "r"(dst), "l"(src));
}
#define CP_COMMIT()   asm volatile("cp.async.commit_group;")
#define CP_WAIT(n)    asm volatile("cp.async.wait_group %0;" :: "n"(n) : "memory")

static __device__ __forceinline__ float4 lds128(uint32_t addr) {
    float4 v;
    asm volatile("ld.shared.v4.f32 {%0,%1,%2,%3}, [%4];"
                 : "=f"(v.x), "=f"(v.y), "=f"(v.z), "=f"(v.w) : "r"(addr));
    return v;
}
static __device__ __forceinline__ void sts64(uint32_t addr, uint32_t w0, uint32_t w1) {
    asm volatile("st.shared.v2.b32 [%0], {%1, %2};" :: "r"(addr), "r"(w0), "r"(w1));
}

#define LDSM4(r, a) \
    asm volatile("ldmatrix.sync.aligned.m8n8.x4.shared.b16 {%0,%1,%2,%3}, [%4];" \
        : "=r"((r)[0]), "=r"((r)[1]), "=r"((r)[2]), "=r"((r)[3]) : "r"(a))
#define LDSM4T(r, a) \
    asm volatile("ldmatrix.sync.aligned.m8n8.x4.trans.shared.b16 {%0,%1,%2,%3}, [%4];" \
        : "=r"((r)[0]), "=r"((r)[1]), "=r"((r)[2]), "=r"((r)[3]) : "r"(a))

static __device__ __forceinline__ void mma_f16(float* c, const uint32_t* a,
                                               uint32_t b0, uint32_t b1) {
    asm volatile(
        "mma.sync.aligned.m16n8k16.row.col.f32.f16.f16.f32 "
        "{%0,%1,%2,%3}, {%4,%5,%6,%7}, {%8,%9}, {%0,%1,%2,%3};\n"
        : "+f"(c[0]), "+f"(c[1]), "+f"(c[2]), "+f"(c[3])
        : "r"(a[0]), "r"(a[1]), "r"(a[2]), "r"(a[3]), "r"(b0), "r"(b1));
}

__global__ __launch_bounds__(256, 2)
void grouped_gemm_kernel(const float* __restrict__ X, const float* __restrict__ W,
                         const int* __restrict__ counts, float* __restrict__ Y) {
    extern __shared__ char smem[];       // [3 raw f32 stages][2 fp16 stages]

    const int g  = blockIdx.z;
    const int mt = blockIdx.y;
    const int nt = blockIdx.x;
    const int cnt = counts[g];
    if (mt * BM >= cnt) return;
    const int gstart = g_starts[g];

    const int t    = threadIdx.x;
    const int lane = t & 31;
    const int wid  = t >> 5;
    const int warpM = wid & 1;
    const int warpN = wid >> 1;
    const int m0 = warpM * 32;
    const int n0 = warpN * 64;
    const int tg  = lane >> 2;
    const int tig = lane & 3;

    // ---- cp.async mapping (f32 raw) ----
    const int a_row = t >> 2;            // 0..63
    const int a_kv  = t & 3;
    long long arow = (long long)gstart + mt * BM + a_row;
    if (arow > T_ - 1) arow = T_ - 1;    // clamp; masked in epilogue
    const float* Ag = X + arow * DIN_ + a_kv * 4;
    const uint32_t aRawOff = (uint32_t)(a_row * 64 + a_kv * 16);

    const int b_k0 = t >> 6;             // 0..3
    const int b_nv = t & 63;
    int bcol = nt * BN + b_nv * 4;
    if (bcol > DOUT_ - 4) bcol = DOUT_ - 4;   // clamp tail tile
    const float* Bg = W + (long long)g * DIN_ * DOUT_ + bcol;
    const uint32_t bRawOff = (uint32_t)(b_k0 * 1024 + b_nv * 16);

    const uint32_t sBase  = smem_u32(smem);
    const uint32_t fpBase = sBase + NSTAGE * RAW_STG;

    auto issue_stage = [&](int kt) {
        const uint32_t stg = sBase + (uint32_t)((kt % NSTAGE) * RAW_STG);
        const int k0 = kt * BK;
        cp16(stg + aRawOff, Ag + k0);
        #pragma unroll
        for (int i = 0; i < 4; ++i)
            cp16(stg + RAW_A + bRawOff + (uint32_t)(4 * i * 1024),
                 Bg + (long long)(k0 + b_k0 + 4 * i) * DOUT_);
    };

    // convert raw f32 stage -> fp16 stage
    const uint32_t aFpOff = (uint32_t)(a_row * LDA_B + a_kv * 8);
    const uint32_t bFpOff = (uint32_t)(b_k0 * LDB_B + b_nv * 8);
    auto convert_stage = [&](int kt) {
        const uint32_t raw = sBase + (uint32_t)((kt % NSTAGE) * RAW_STG);
        const uint32_t fp  = fpBase + (uint32_t)((kt & 1) * FP_STG);
        float4 v = lds128(raw + aRawOff);
        sts64(fp + aFpOff, pack_h2(v.x, v.y), pack_h2(v.z, v.w));
        #pragma unroll
        for (int i = 0; i < 4; ++i) {
            float4 b = lds128(raw + RAW_A + bRawOff + (uint32_t)(4 * i * 1024));
            sts64(fp + FP_A + bFpOff + (uint32_t)(4 * i * LDB_B),
                  pack_h2(b.x, b.y), pack_h2(b.z, b.w));
        }
    };

    // ---- ldmatrix addresses (within one fp16 stage) ----
    const int l15 = lane & 15;
    const int lhi = lane >> 4;
    uint32_t aoff[2];
    #pragma unroll
    for (int mf = 0; mf < 2; ++mf)
        aoff[mf] = (uint32_t)((m0 + mf * 16 + l15) * LDA_B + lhi * 16);
    uint32_t boff[4];
    #pragma unroll
    for (int p = 0; p < 4; ++p)
        boff[p] = (uint32_t)(FP_A + l15 * LDB_B + (n0 + p * 16 + lhi * 8) * 2);

    float acc[2][8][4];
    #pragma unroll
    for (int mf = 0; mf < 2; ++mf)
        #pragma unroll
        for (int nf = 0; nf < 8; ++nf)
            #pragma unroll
            for (int i = 0; i < 4; ++i) acc[mf][nf][i] = 0.0f;

    // prologue: raw stages 0,1,2 in flight; convert stage 0
    issue_stage(0); CP_COMMIT();
    issue_stage(1); CP_COMMIT();
    CP_WAIT(1);                          // raw 0 resident
    __syncthreads();
    convert_stage(0);
    issue_stage(2); CP_COMMIT();

    for (int kt = 0; kt < NK; ++kt) {
        CP_WAIT(1);                      // raw kt+1 resident (raw kt+2 may be in flight)
        __syncthreads();                 // fp16[(kt+1)&1] readers (iter kt-1) done;
                                         // raw slot kt%3 converters (iter kt-1) done

        if (kt + 1 < NK) convert_stage(kt + 1);
        if (kt + 3 < NK) issue_stage(kt + 3);
        CP_COMMIT();                     // exactly one group per iter (may be empty)

        const uint32_t fp = fpBase + (uint32_t)((kt & 1) * FP_STG);
        uint32_t af[2][4], bf[4][4];
        LDSM4(af[0], fp + aoff[0]);
        LDSM4(af[1], fp + aoff[1]);
        #pragma unroll
        for (int p = 0; p < 4; ++p)
            LDSM4T(bf[p], fp + boff[p]);

        #pragma unroll
        for (int p = 0; p < 4; ++p)
            #pragma unroll
            for (int mf = 0; mf < 2; ++mf) {
                mma_f16(acc[mf][2 * p],     af[mf], bf[p][0], bf[p][1]);
                mma_f16(acc[mf][2 * p + 1], af[mf], bf[p][2], bf[p][3]);
            }
    }

    // ---- epilogue: predicated float2 stores ----
    #pragma unroll
    for (int mf = 0; mf < 2; ++mf) {
        const int r0 = mt * BM + m0 + mf * 16 + tg;
        const int r1 = r0 + 8;
        #pragma unroll
        for (int nf = 0; nf < 8; ++nf) {
            const int col = nt * BN + n0 + nf * 8 + tig * 2;
            if (col < DOUT_) {
                if (r0 < cnt) {
                    float2 v = make_float2(acc[mf][nf][0], acc[mf][nf][1]);
                    *(float2*)&Y[(long long)(gstart + r0) * DOUT_ + col] = v;
                }
                if (r1 < cnt) {
                    float2 v = make_float2(acc[mf][nf][2], acc[mf][nf][3]);
                    *(float2*)&Y[(long long)(gstart + r1) * DOUT_ + col] = v;
                }
            }
        }
    }
}

extern "C" void kernel_launch(void* const* d_in, const int* in_sizes, int n_in,
                              void* d_out, int out_size) {
    const float* x    = (const float*)d_in[0];
    const float* w    = (const float*)d_in[1];
    const int*   cnts = (const int*)d_in[2];
    float* y = (float*)d_out;

    starts_kernel<<<1, 32>>>(cnts);

    cudaFuncSetAttribute(grouped_gemm_kernel,
                         cudaFuncAttributeMaxDynamicSharedMemorySize, SMEM_TOTAL);
    dim3 grid(NT_N, CAP_ / BM, G_);      // (7, 4, 64)
    grouped_gemm_kernel<<<grid, 256, SMEM_TOTAL>>>(x, w, cnts, y);
}